// round 9
// baseline (speedup 1.0000x reference)
#include <cuda_runtime.h>
#include <cstdint>

#define MTOK 16384
#define FDIM 4096
#define CDIM 1024
#define NQ 8

#define BM 128
#define BN 256
#define BK 32
#define STAGES 4
#define KTILES (FDIM / BK)               // 128
#define ROWF 36                          // padded floats/row: conflict-free LDSM
#define A_FLOATS (BM * ROWF)             // 4608
#define B_FLOATS (BN * ROWF)             // 9216
#define STAGE_FLOATS (A_FLOATS + B_FLOATS)           // 13824
#define SMEM_TOTAL (STAGES * STAGE_FLOATS * 4)       // 221184 B

// ---- scratch (device globals; allocation is forbidden) ----
__device__ __align__(128) float g_q[MTOK * NQ];                 // 512 KB
__device__ __align__(128) float g_h[(size_t)MTOK * FDIM];       // 256 MB
__device__ __align__(128) float g_w2r[(size_t)CDIM * FDIM];     // 16 MB

__device__ __forceinline__ uint32_t smem_u32(const void* p) {
    uint32_t a;
    asm("{ .reg .u64 t; cvta.to.shared.u64 t, %1; cvt.u32.u64 %0, t; }" : "=r"(a) : "l"(p));
    return a;
}

__device__ __forceinline__ float tf32r(float x) {
    uint32_t y;
    asm("cvt.rna.tf32.f32 %0, %1;" : "=r"(y) : "f"(x));
    return __uint_as_float(y);
}

__device__ __forceinline__ void cp_async16(uint32_t dst, const void* src) {
    asm volatile("cp.async.cg.shared.global [%0], [%1], 16;" :: "r"(dst), "l"(src));
}
#define CP_COMMIT() asm volatile("cp.async.commit_group;" ::: "memory")
#define CP_WAIT2()  asm volatile("cp.async.wait_group 2;" ::: "memory")

__device__ __forceinline__ void mma_tf32(float* c, const uint32_t* a, uint32_t b0, uint32_t b1) {
    asm volatile(
        "mma.sync.aligned.m16n8k8.row.col.f32.tf32.tf32.f32 "
        "{%0,%1,%2,%3}, {%4,%5,%6,%7}, {%8,%9}, {%0,%1,%2,%3};"
        : "+f"(c[0]), "+f"(c[1]), "+f"(c[2]), "+f"(c[3])
        : "r"(a[0]), "r"(a[1]), "r"(a[2]), "r"(a[3]), "r"(b0), "r"(b1));
}

// ldmatrix.x4 on b16 8x8 tiles == four 8x4 b32 tiles; thread map (lane/4, lane%4)
// matches the tf32 m16n8k8 fragment layout exactly (validated by R7 scalar loads).
__device__ __forceinline__ void ldsm4(uint32_t* r, uint32_t addr) {
    asm volatile("ldmatrix.sync.aligned.m8n8.x4.shared.b16 {%0,%1,%2,%3}, [%4];"
                 : "=r"(r[0]), "=r"(r[1]), "=r"(r[2]), "=r"(r[3]) : "r"(addr));
}

// ==================== pass 0: q = cumprod(cos(x[:, :8])) ====================
__global__ void __launch_bounds__(256) q_kernel(const float* __restrict__ x) {
    int tok = blockIdx.x * 256 + threadIdx.x;
    const float4* xp = (const float4*)(x + (size_t)tok * CDIM);
    float4 a = xp[0], b = xp[1];
    float q0 = cosf(a.x);
    float q1 = q0 * cosf(a.y);
    float q2 = q1 * cosf(a.z);
    float q3 = q2 * cosf(a.w);
    float q4 = q3 * cosf(b.x);
    float q5 = q4 * cosf(b.y);
    float q6 = q5 * cosf(b.z);
    float q7 = q6 * cosf(b.w);
    float4* qp = (float4*)(g_q + (size_t)tok * NQ);
    qp[0] = make_float4(q0, q1, q2, q3);
    qp[1] = make_float4(q4, q5, q6, q7);
}

// ==================== pass 0b: w2 rounded to tf32-nearest ====================
__global__ void __launch_bounds__(256) round_w2_kernel(const float* __restrict__ w2) {
    size_t i = (size_t)(blockIdx.x * 256 + threadIdx.x) * 4;
    float4 v = *(const float4*)(w2 + i);
    v.x = tf32r(v.x); v.y = tf32r(v.y); v.z = tf32r(v.z); v.w = tf32r(v.w);
    *(float4*)(g_w2r + i) = v;
}

// ==================== pass 1: h = relu(q @ w1^T + b1), tf32-rounded ====================
__global__ void __launch_bounds__(256) h_kernel(const float* __restrict__ w1,
                                                const float* __restrict__ b1) {
    __shared__ float qs[512 * NQ];  // 16 KB
    int t = threadIdx.x;
    const float4* qg = (const float4*)(g_q + (size_t)blockIdx.y * 512 * NQ);
    float4* qs4 = (float4*)qs;
#pragma unroll
    for (int i = 0; i < 4; i++) qs4[t + i * 256] = qg[t + i * 256];
    __syncthreads();

    int f = blockIdx.x * 32 + (t & 31);
    int tok0 = (t >> 5) * 64;
    float4 wa = __ldg((const float4*)(w1 + (size_t)f * NQ));
    float4 wb = __ldg((const float4*)(w1 + (size_t)f * NQ + 4));
    float bias = __ldg(b1 + f);
    float* hp = g_h + ((size_t)(blockIdx.y * 512 + tok0)) * FDIM + f;

#pragma unroll 8
    for (int i = 0; i < 64; i++) {
        const float4* qr = (const float4*)(qs + (tok0 + i) * NQ);
        float4 qa = qr[0], qb = qr[1];
        float v = bias;
        v = fmaf(qa.x, wa.x, v); v = fmaf(qa.y, wa.y, v);
        v = fmaf(qa.z, wa.z, v); v = fmaf(qa.w, wa.w, v);
        v = fmaf(qb.x, wb.x, v); v = fmaf(qb.y, wb.y, v);
        v = fmaf(qb.z, wb.z, v); v = fmaf(qb.w, wb.w, v);
        hp[(size_t)i * FDIM] = tf32r(fmaxf(v, 0.0f));
    }
}

// ==================== pass 2: out = h @ w2^T + b2 (mma.sync tf32) ====================
// CTA 128x256, 8 warps in 2(m) x 4(n), warp tile 64x64 -> 8 MAC/byte of smem
// traffic: exactly balanced against the 128 B/cyc crossbar.
__device__ __forceinline__ void load_tile(uint32_t stage_b, int m0, int n0, int k0, int tid) {
#pragma unroll
    for (int i = 0; i < 4; i++) {
        int idx = tid + i * 256;
        int row = idx >> 3, c4 = idx & 7;
        cp_async16(stage_b + (row * ROWF + c4 * 4) * 4,
                   g_h + (size_t)(m0 + row) * FDIM + k0 + c4 * 4);
    }
#pragma unroll
    for (int i = 0; i < 8; i++) {
        int idx = tid + i * 256;
        int row = idx >> 3, c4 = idx & 7;
        cp_async16(stage_b + (A_FLOATS + row * ROWF + c4 * 4) * 4,
                   g_w2r + (size_t)(n0 + row) * FDIM + k0 + c4 * 4);
    }
}

__global__ void __launch_bounds__(256, 1) gemm2_kernel(const float* __restrict__ b2,
                                                       float* __restrict__ out) {
    extern __shared__ __align__(16) uint32_t sm[];
    uint32_t sb = smem_u32(sm);
    int tid = threadIdx.x, wid = tid >> 5, lane = tid & 31;
    int wm = wid & 1, wn = wid >> 1;          // warp grid 2 x 4; warp tile 64 x 64
    int g = lane >> 2, t4 = lane & 3;
    int lane15 = lane & 15, khalf = (lane >> 4) << 2;   // ldmatrix per-lane row/col select
    int m0 = blockIdx.y * BM, n0 = blockIdx.x * BN;

    float acc[4][8][4];
#pragma unroll
    for (int mt = 0; mt < 4; mt++)
#pragma unroll
        for (int nt = 0; nt < 8; nt++)
#pragma unroll
            for (int r = 0; r < 4; r++) acc[mt][nt][r] = 0.0f;

    // prologue: tiles 0..2 into stages 0..2
#pragma unroll
    for (int t = 0; t < 3; t++) {
        load_tile(sb + t * STAGE_FLOATS * 4, m0, n0, t * BK, tid);
        CP_COMMIT();
    }

    // per-lane ldmatrix base offsets (bytes)
    const uint32_t aOff = ((uint32_t)(wm * 64 + lane15) * ROWF + khalf) * 4;
    const uint32_t bOff = ((uint32_t)A_FLOATS + (uint32_t)(wn * 64 + lane15) * ROWF + khalf) * 4;

    for (int t = 0; t < KTILES; t++) {
        CP_WAIT2();              // tile t resident (this thread's groups)
        __syncthreads();         // everyone's loads visible; stage (t-1) reads done
        if (t + 3 < KTILES)
            load_tile(sb + ((t + 3) & 3) * STAGE_FLOATS * 4, m0, n0, (t + 3) * BK, tid);
        CP_COMMIT();             // uniform group accounting (empty at tail)

        uint32_t stg = sb + (t & 3) * STAGE_FLOATS * 4;
#pragma unroll
        for (int ks = 0; ks < 4; ks++) {
            uint32_t a[4][4], b[4][4];
#pragma unroll
            for (int mt = 0; mt < 4; mt++)
                ldsm4(a[mt], stg + aOff + (uint32_t)(mt * 16 * ROWF + ks * 8) * 4);
#pragma unroll
            for (int p = 0; p < 4; p++)
                ldsm4(b[p], stg + bOff + (uint32_t)(p * 16 * ROWF + ks * 8) * 4);
#pragma unroll
            for (int mt = 0; mt < 4; mt++)
#pragma unroll
                for (int p = 0; p < 4; p++) {
                    mma_tf32(acc[mt][2 * p],     a[mt], b[p][0], b[p][2]);
                    mma_tf32(acc[mt][2 * p + 1], a[mt], b[p][1], b[p][3]);
                }
        }
    }

    // epilogue: c0/c1 at (row g, cols 2t4..+1), c2/c3 at row g+8
#pragma unroll
    for (int mt = 0; mt < 4; mt++) {
        int mrow = m0 + wm * 64 + mt * 16 + g;
#pragma unroll
        for (int nt = 0; nt < 8; nt++) {
            int nc = n0 + wn * 64 + nt * 8 + 2 * t4;
            float bx = __ldg(b2 + nc), by = __ldg(b2 + nc + 1);
            float2 v0 = make_float2(acc[mt][nt][0] + bx, acc[mt][nt][1] + by);
            float2 v1 = make_float2(acc[mt][nt][2] + bx, acc[mt][nt][3] + by);
            *(float2*)(out + (size_t)mrow * CDIM + nc) = v0;
            *(float2*)(out + (size_t)(mrow + 8) * CDIM + nc) = v1;
        }
    }
}

// ==================== launch ====================
extern "C" void kernel_launch(void* const* d_in, const int* in_sizes, int n_in,
                              void* d_out, int out_size) {
    const float* x  = (const float*)d_in[0];
    // d_in[1] = circuit_params: provably cancels out of the measured expectations
    const float* w1 = (const float*)d_in[2];
    const float* b1 = (const float*)d_in[3];
    const float* w2 = (const float*)d_in[4];
    const float* b2 = (const float*)d_in[5];
    float* out = (float*)d_out;

    q_kernel<<<MTOK / 256, 256>>>(x);
    round_w2_kernel<<<(CDIM * FDIM) / (256 * 4), 256>>>(w2);
    h_kernel<<<dim3(FDIM / 32, MTOK / 512), 256>>>(w1, b1);

    cudaFuncSetAttribute(gemm2_kernel, cudaFuncAttributeMaxDynamicSharedMemorySize, SMEM_TOTAL);
    gemm2_kernel<<<dim3(CDIM / BN, MTOK / BM), 256, SMEM_TOTAL>>>(b2, out);
}

// round 11
// speedup vs baseline: 1.1056x; 1.1056x over previous
#include <cuda_runtime.h>
#include <cstdint>

#define MTOK 16384
#define FDIM 4096
#define CDIM 1024
#define NQ 8

#define BM 128
#define BN 128
#define BK 32
#define STAGES 3
#define KTILES (FDIM / BK)               // 128
#define ROWF 36                          // padded floats/row (144B: 16B-aligned rows, conflict-free LDSM)
#define A_FLOATS (BM * ROWF)             // 4608
#define STAGE_FLOATS (2 * A_FLOATS)      // A then B: 9216
#define SMEM_TOTAL (STAGES * STAGE_FLOATS * 4)   // 110592 B -> 2 CTAs/SM

// ---- scratch (device globals; allocation is forbidden) ----
__device__ __align__(128) float g_q[MTOK * NQ];                 // 512 KB
__device__ __align__(128) float g_h[(size_t)MTOK * FDIM];       // 256 MB
__device__ __align__(128) float g_w2r[(size_t)CDIM * FDIM];     // 16 MB

__device__ __forceinline__ uint32_t smem_u32(const void* p) {
    uint32_t a;
    asm("{ .reg .u64 t; cvta.to.shared.u64 t, %1; cvt.u32.u64 %0, t; }" : "=r"(a) : "l"(p));
    return a;
}

__device__ __forceinline__ float tf32r(float x) {
    uint32_t y;
    asm("cvt.rna.tf32.f32 %0, %1;" : "=r"(y) : "f"(x));
    return __uint_as_float(y);
}

__device__ __forceinline__ void cp_async16(uint32_t dst, const void* src) {
    asm volatile("cp.async.cg.shared.global [%0], [%1], 16;" :: "r"(dst), "l"(src));
}
#define CP_COMMIT() asm volatile("cp.async.commit_group;" ::: "memory")
#define CP_WAIT2()  asm volatile("cp.async.wait_group 2;" ::: "memory")

__device__ __forceinline__ void mma_tf32(float* c, const uint32_t* a, uint32_t b0, uint32_t b1) {
    asm volatile(
        "mma.sync.aligned.m16n8k8.row.col.f32.tf32.tf32.f32 "
        "{%0,%1,%2,%3}, {%4,%5,%6,%7}, {%8,%9}, {%0,%1,%2,%3};"
        : "+f"(c[0]), "+f"(c[1]), "+f"(c[2]), "+f"(c[3])
        : "r"(a[0]), "r"(a[1]), "r"(a[2]), "r"(a[3]), "r"(b0), "r"(b1));
}

// ldmatrix.x4 on b16 8x8 tiles == four 8x4 b32 tiles; thread map (lane/4, lane%4)
// matches the tf32 m16n8k8 fragment layout (numerically validated in R9: same rel_err).
__device__ __forceinline__ void ldsm4(uint32_t* r, uint32_t addr) {
    asm volatile("ldmatrix.sync.aligned.m8n8.x4.shared.b16 {%0,%1,%2,%3}, [%4];"
                 : "=r"(r[0]), "=r"(r[1]), "=r"(r[2]), "=r"(r[3]) : "r"(addr));
}

// ==================== pass 0: q = cumprod(cos(x[:, :8])) ====================
__global__ void __launch_bounds__(256) q_kernel(const float* __restrict__ x) {
    int tok = blockIdx.x * 256 + threadIdx.x;
    const float4* xp = (const float4*)(x + (size_t)tok * CDIM);
    float4 a = xp[0], b = xp[1];
    float q0 = cosf(a.x);
    float q1 = q0 * cosf(a.y);
    float q2 = q1 * cosf(a.z);
    float q3 = q2 * cosf(a.w);
    float q4 = q3 * cosf(b.x);
    float q5 = q4 * cosf(b.y);
    float q6 = q5 * cosf(b.z);
    float q7 = q6 * cosf(b.w);
    float4* qp = (float4*)(g_q + (size_t)tok * NQ);
    qp[0] = make_float4(q0, q1, q2, q3);
    qp[1] = make_float4(q4, q5, q6, q7);
}

// ==================== pass 0b: w2 rounded to tf32-nearest ====================
__global__ void __launch_bounds__(256) round_w2_kernel(const float* __restrict__ w2) {
    size_t i = (size_t)(blockIdx.x * 256 + threadIdx.x) * 4;
    float4 v = *(const float4*)(w2 + i);
    v.x = tf32r(v.x); v.y = tf32r(v.y); v.z = tf32r(v.z); v.w = tf32r(v.w);
    *(float4*)(g_w2r + i) = v;
}

// ==================== pass 1: h = relu(q @ w1^T + b1), tf32-rounded ====================
__global__ void __launch_bounds__(256) h_kernel(const float* __restrict__ w1,
                                                const float* __restrict__ b1) {
    __shared__ float qs[512 * NQ];  // 16 KB
    int t = threadIdx.x;
    const float4* qg = (const float4*)(g_q + (size_t)blockIdx.y * 512 * NQ);
    float4* qs4 = (float4*)qs;
#pragma unroll
    for (int i = 0; i < 4; i++) qs4[t + i * 256] = qg[t + i * 256];
    __syncthreads();

    int f = blockIdx.x * 32 + (t & 31);
    int tok0 = (t >> 5) * 64;
    float4 wa = __ldg((const float4*)(w1 + (size_t)f * NQ));
    float4 wb = __ldg((const float4*)(w1 + (size_t)f * NQ + 4));
    float bias = __ldg(b1 + f);
    float* hp = g_h + ((size_t)(blockIdx.y * 512 + tok0)) * FDIM + f;

#pragma unroll 8
    for (int i = 0; i < 64; i++) {
        const float4* qr = (const float4*)(qs + (tok0 + i) * NQ);
        float4 qa = qr[0], qb = qr[1];
        float v = bias;
        v = fmaf(qa.x, wa.x, v); v = fmaf(qa.y, wa.y, v);
        v = fmaf(qa.z, wa.z, v); v = fmaf(qa.w, wa.w, v);
        v = fmaf(qb.x, wb.x, v); v = fmaf(qb.y, wb.y, v);
        v = fmaf(qb.z, wb.z, v); v = fmaf(qb.w, wb.w, v);
        hp[(size_t)i * FDIM] = tf32r(fmaxf(v, 0.0f));
    }
}

// ==================== pass 2: out = h @ w2^T + b2 (mma.sync tf32) ====================
// CTA 128x128 with FOUR warps (2x2 grid), warp tile 64x64 (8 MAC/byte of smem reads).
// 2 CTAs/SM: syncs stall only half the SM's warps (R7's overlap + R9's traffic ratio).
__device__ __forceinline__ void load_tile(uint32_t stage_b, int m0, int n0, int k0, int tid) {
#pragma unroll
    for (int i = 0; i < 8; i++) {
        int idx = tid + i * 128;
        int row = idx >> 3, c4 = idx & 7;
        cp_async16(stage_b + (row * ROWF + c4 * 4) * 4,
                   g_h + (size_t)(m0 + row) * FDIM + k0 + c4 * 4);
    }
#pragma unroll
    for (int i = 0; i < 8; i++) {
        int idx = tid + i * 128;
        int row = idx >> 3, c4 = idx & 7;
        cp_async16(stage_b + (A_FLOATS + row * ROWF + c4 * 4) * 4,
                   g_w2r + (size_t)(n0 + row) * FDIM + k0 + c4 * 4);
    }
}

__global__ void __launch_bounds__(128, 2) gemm2_kernel(const float* __restrict__ b2,
                                                       float* __restrict__ out) {
    extern __shared__ __align__(16) uint32_t sm[];
    uint32_t sb = smem_u32(sm);
    int tid = threadIdx.x, wid = tid >> 5, lane = tid & 31;
    int wm = wid & 1, wn = wid >> 1;          // warp grid 2 x 2; warp tile 64 x 64
    int g = lane >> 2, t4 = lane & 3;
    int lane15 = lane & 15, khalf = (lane >> 4) << 2;   // ldmatrix per-lane row / k-half
    int m0 = blockIdx.y * BM, n0 = blockIdx.x * BN;

    float acc[4][8][4];
#pragma unroll
    for (int mt = 0; mt < 4; mt++)
#pragma unroll
        for (int nt = 0; nt < 8; nt++)
#pragma unroll
            for (int r = 0; r < 4; r++) acc[mt][nt][r] = 0.0f;

    // prologue: tiles 0,1 into stages 0,1
    load_tile(sb, m0, n0, 0, tid);                     CP_COMMIT();
    load_tile(sb + STAGE_FLOATS * 4, m0, n0, BK, tid); CP_COMMIT();

    const uint32_t aOff = ((uint32_t)(wm * 64 + lane15) * ROWF + khalf) * 4;
    const uint32_t bOff = ((uint32_t)A_FLOATS + (uint32_t)(wn * 64 + lane15) * ROWF + khalf) * 4;

    int s = 0, sw = 2;   // read stage, write stage (incremental mod-3)
    for (int t = 0; t < KTILES; t++) {
        if (t + 2 < KTILES)
            load_tile(sb + sw * STAGE_FLOATS * 4, m0, n0, (t + 2) * BK, tid);
        CP_COMMIT();             // uniform group accounting (empty at tail)
        CP_WAIT2();              // tile t resident (this thread's groups)
        __syncthreads();         // everyone's loads visible

        uint32_t stg = sb + s * STAGE_FLOATS * 4;
#pragma unroll
        for (int ks = 0; ks < 4; ks++) {
            uint32_t a[4][4], b[4][4];
#pragma unroll
            for (int mt = 0; mt < 4; mt++)
                ldsm4(a[mt], stg + aOff + (uint32_t)(mt * 16 * ROWF + ks * 8) * 4);
#pragma unroll
            for (int p = 0; p < 4; p++)
                ldsm4(b[p], stg + bOff + (uint32_t)(p * 16 * ROWF + ks * 8) * 4);
#pragma unroll
            for (int mt = 0; mt < 4; mt++)
#pragma unroll
                for (int p = 0; p < 4; p++) {
                    mma_tf32(acc[mt][2 * p],     a[mt], b[p][0], b[p][2]);
                    mma_tf32(acc[mt][2 * p + 1], a[mt], b[p][1], b[p][3]);
                }
        }
        __syncthreads();         // stage s reads done -> reusable as write target
        s = (s == 2) ? 0 : s + 1;
        sw = (sw == 2) ? 0 : sw + 1;
    }

    // epilogue: c0/c1 at (row g, cols 2t4..+1), c2/c3 at row g+8
#pragma unroll
    for (int mt = 0; mt < 4; mt++) {
        int mrow = m0 + wm * 64 + mt * 16 + g;
#pragma unroll
        for (int nt = 0; nt < 8; nt++) {
            int nc = n0 + wn * 64 + nt * 8 + 2 * t4;
            float bx = __ldg(b2 + nc), by = __ldg(b2 + nc + 1);
            float2 v0 = make_float2(acc[mt][nt][0] + bx, acc[mt][nt][1] + by);
            float2 v1 = make_float2(acc[mt][nt][2] + bx, acc[mt][nt][3] + by);
            *(float2*)(out + (size_t)mrow * CDIM + nc) = v0;
            *(float2*)(out + (size_t)(mrow + 8) * CDIM + nc) = v1;
        }
    }
}

// ==================== launch ====================
extern "C" void kernel_launch(void* const* d_in, const int* in_sizes, int n_in,
                              void* d_out, int out_size) {
    const float* x  = (const float*)d_in[0];
    // d_in[1] = circuit_params: provably cancels out of the measured expectations
    const float* w1 = (const float*)d_in[2];
    const float* b1 = (const float*)d_in[3];
    const float* w2 = (const float*)d_in[4];
    const float* b2 = (const float*)d_in[5];
    float* out = (float*)d_out;

    q_kernel<<<MTOK / 256, 256>>>(x);
    round_w2_kernel<<<(CDIM * FDIM) / (256 * 4), 256>>>(w2);
    h_kernel<<<dim3(FDIM / 32, MTOK / 512), 256>>>(w1, b1);

    cudaFuncSetAttribute(gemm2_kernel, cudaFuncAttributeMaxDynamicSharedMemorySize, SMEM_TOTAL);
    gemm2_kernel<<<dim3(CDIM / BN, MTOK / BM), 128, SMEM_TOTAL>>>(b2, out);
}

// round 13
// speedup vs baseline: 1.1076x; 1.0018x over previous
#include <cuda_runtime.h>
#include <cstdint>

#define MTOK 16384
#define FDIM 4096
#define CDIM 1024
#define NQ 8

#define BM 128
#define BN 128
#define BK 32
#define STAGES 3
#define KTILES (FDIM / BK)               // 128
#define ROWF 36                          // padded floats/row (144B): LDSM phase hits all 32 banks once
#define A_FLOATS (BM * ROWF)             // 4608
#define STAGE_FLOATS (2 * A_FLOATS)      // A then B: 9216
#define SMEM_TOTAL (STAGES * STAGE_FLOATS * 4)   // 110592 B -> 2 CTAs/SM

// ---- scratch (device globals; allocation is forbidden) ----
__device__ __align__(128) float g_q[MTOK * NQ];                 // 512 KB
__device__ __align__(128) float g_h[(size_t)MTOK * FDIM];       // 256 MB
__device__ __align__(128) float g_w2r[(size_t)CDIM * FDIM];     // 16 MB

__device__ __forceinline__ uint32_t smem_u32(const void* p) {
    uint32_t a;
    asm("{ .reg .u64 t; cvta.to.shared.u64 t, %1; cvt.u32.u64 %0, t; }" : "=r"(a) : "l"(p));
    return a;
}

__device__ __forceinline__ float tf32r(float x) {
    uint32_t y;
    asm("cvt.rna.tf32.f32 %0, %1;" : "=r"(y) : "f"(x));
    return __uint_as_float(y);
}

__device__ __forceinline__ void cp_async16(uint32_t dst, const void* src) {
    asm volatile("cp.async.cg.shared.global [%0], [%1], 16;" :: "r"(dst), "l"(src));
}
#define CP_COMMIT() asm volatile("cp.async.commit_group;" ::: "memory")
#define CP_WAIT2()  asm volatile("cp.async.wait_group 2;" ::: "memory")

__device__ __forceinline__ void mma_tf32(float* c, const uint32_t* a, uint32_t b0, uint32_t b1) {
    asm volatile(
        "mma.sync.aligned.m16n8k8.row.col.f32.tf32.tf32.f32 "
        "{%0,%1,%2,%3}, {%4,%5,%6,%7}, {%8,%9}, {%0,%1,%2,%3};"
        : "+f"(c[0]), "+f"(c[1]), "+f"(c[2]), "+f"(c[3])
        : "r"(a[0]), "r"(a[1]), "r"(a[2]), "r"(a[3]), "r"(b0), "r"(b1));
}

// ldmatrix.x4 on b16 8x8 tiles == four 8x4 b32 tiles; fragment map validated (R9/R11 rel_err).
__device__ __forceinline__ void ldsm4(uint32_t* r, uint32_t addr) {
    asm volatile("ldmatrix.sync.aligned.m8n8.x4.shared.b16 {%0,%1,%2,%3}, [%4];"
                 : "=r"(r[0]), "=r"(r[1]), "=r"(r[2]), "=r"(r[3]) : "r"(addr));
}

// ==================== pass 0: q = cumprod(cos(x[:, :8])) ====================
__global__ void __launch_bounds__(256) q_kernel(const float* __restrict__ x) {
    int tok = blockIdx.x * 256 + threadIdx.x;
    const float4* xp = (const float4*)(x + (size_t)tok * CDIM);
    float4 a = xp[0], b = xp[1];
    float q0 = cosf(a.x);
    float q1 = q0 * cosf(a.y);
    float q2 = q1 * cosf(a.z);
    float q3 = q2 * cosf(a.w);
    float q4 = q3 * cosf(b.x);
    float q5 = q4 * cosf(b.y);
    float q6 = q5 * cosf(b.z);
    float q7 = q6 * cosf(b.w);
    float4* qp = (float4*)(g_q + (size_t)tok * NQ);
    qp[0] = make_float4(q0, q1, q2, q3);
    qp[1] = make_float4(q4, q5, q6, q7);
}

// ==================== pass 0b: w2 rounded to tf32-nearest ====================
__global__ void __launch_bounds__(256) round_w2_kernel(const float* __restrict__ w2) {
    size_t i = (size_t)(blockIdx.x * 256 + threadIdx.x) * 4;
    float4 v = *(const float4*)(w2 + i);
    v.x = tf32r(v.x); v.y = tf32r(v.y); v.z = tf32r(v.z); v.w = tf32r(v.w);
    *(float4*)(g_w2r + i) = v;
}

// ==================== pass 1: h = relu(q @ w1^T + b1), tf32-rounded ====================
__global__ void __launch_bounds__(256) h_kernel(const float* __restrict__ w1,
                                                const float* __restrict__ b1) {
    __shared__ float qs[512 * NQ];  // 16 KB
    int t = threadIdx.x;
    const float4* qg = (const float4*)(g_q + (size_t)blockIdx.y * 512 * NQ);
    float4* qs4 = (float4*)qs;
#pragma unroll
    for (int i = 0; i < 4; i++) qs4[t + i * 256] = qg[t + i * 256];
    __syncthreads();

    int f = blockIdx.x * 32 + (t & 31);
    int tok0 = (t >> 5) * 64;
    float4 wa = __ldg((const float4*)(w1 + (size_t)f * NQ));
    float4 wb = __ldg((const float4*)(w1 + (size_t)f * NQ + 4));
    float bias = __ldg(b1 + f);
    float* hp = g_h + ((size_t)(blockIdx.y * 512 + tok0)) * FDIM + f;

#pragma unroll 8
    for (int i = 0; i < 64; i++) {
        const float4* qr = (const float4*)(qs + (tok0 + i) * NQ);
        float4 qa = qr[0], qb = qr[1];
        float v = bias;
        v = fmaf(qa.x, wa.x, v); v = fmaf(qa.y, wa.y, v);
        v = fmaf(qa.z, wa.z, v); v = fmaf(qa.w, wa.w, v);
        v = fmaf(qb.x, wb.x, v); v = fmaf(qb.y, wb.y, v);
        v = fmaf(qb.z, wb.z, v); v = fmaf(qb.w, wb.w, v);
        hp[(size_t)i * FDIM] = tf32r(fmaxf(v, 0.0f));
    }
}

// ==================== pass 2: out = h @ w2^T + b2 (mma.sync tf32) ====================
// CTA 128x128, 4 warps (2x2), warp tile 64x64; 2 CTAs/SM. Fragments are
// double-buffered across k-steps so LDSM latency hides under the MMA block.
__device__ __forceinline__ void load_tile(uint32_t stage_b, int m0, int n0, int k0, int tid) {
#pragma unroll
    for (int i = 0; i < 8; i++) {
        int idx = tid + i * 128;
        int row = idx >> 3, c4 = idx & 7;
        cp_async16(stage_b + (row * ROWF + c4 * 4) * 4,
                   g_h + (size_t)(m0 + row) * FDIM + k0 + c4 * 4);
    }
#pragma unroll
    for (int i = 0; i < 8; i++) {
        int idx = tid + i * 128;
        int row = idx >> 3, c4 = idx & 7;
        cp_async16(stage_b + (A_FLOATS + row * ROWF + c4 * 4) * 4,
                   g_w2r + (size_t)(n0 + row) * FDIM + k0 + c4 * 4);
    }
}

__global__ void __launch_bounds__(128, 2) gemm2_kernel(const float* __restrict__ b2,
                                                       float* __restrict__ out) {
    extern __shared__ __align__(16) uint32_t sm[];
    uint32_t sb = smem_u32(sm);
    int tid = threadIdx.x, wid = tid >> 5, lane = tid & 31;
    int wm = wid & 1, wn = wid >> 1;          // warp grid 2 x 2; warp tile 64 x 64
    int g = lane >> 2, t4 = lane & 3;
    int lane15 = lane & 15, khalf = (lane >> 4) << 2;
    int m0 = blockIdx.y * BM, n0 = blockIdx.x * BN;

    float acc[4][8][4];
#pragma unroll
    for (int mt = 0; mt < 4; mt++)
#pragma unroll
        for (int nt = 0; nt < 8; nt++)
#pragma unroll
            for (int r = 0; r < 4; r++) acc[mt][nt][r] = 0.0f;

    // prologue: tiles 0,1 into stages 0,1
    load_tile(sb, m0, n0, 0, tid);                     CP_COMMIT();
    load_tile(sb + STAGE_FLOATS * 4, m0, n0, BK, tid); CP_COMMIT();

    const uint32_t aOff = ((uint32_t)(wm * 64 + lane15) * ROWF + khalf) * 4;
    const uint32_t bOff = ((uint32_t)A_FLOATS + (uint32_t)(wn * 64 + lane15) * ROWF + khalf) * 4;

    uint32_t fa[2][4][4], fb[2][4][4];

#define LOAD_FRAGS(buf, stg, ks) do {                                              \
        _Pragma("unroll")                                                          \
        for (int _mt = 0; _mt < 4; _mt++)                                          \
            ldsm4(fa[buf][_mt], (stg) + aOff + (uint32_t)(_mt * 16 * ROWF + (ks) * 8) * 4); \
        _Pragma("unroll")                                                          \
        for (int _p = 0; _p < 4; _p++)                                             \
            ldsm4(fb[buf][_p], (stg) + bOff + (uint32_t)(_p * 16 * ROWF + (ks) * 8) * 4);   \
    } while (0)

#define MMA_BLOCK(buf) do {                                                        \
        _Pragma("unroll")                                                          \
        for (int _mt = 0; _mt < 4; _mt++)                                          \
            _Pragma("unroll")                                                      \
            for (int _p = 0; _p < 4; _p++) {                                       \
                mma_tf32(acc[_mt][2 * _p],     fa[buf][_mt], fb[buf][_p][0], fb[buf][_p][2]); \
                mma_tf32(acc[_mt][2 * _p + 1], fa[buf][_mt], fb[buf][_p][1], fb[buf][_p][3]); \
            }                                                                      \
    } while (0)

    int s = 0, sw = 2;   // read stage, write stage (incremental mod-3)
    for (int t = 0; t < KTILES; t++) {
        if (t + 2 < KTILES)
            load_tile(sb + sw * STAGE_FLOATS * 4, m0, n0, (t + 2) * BK, tid);
        CP_COMMIT();             // uniform group accounting (empty at tail)
        CP_WAIT2();              // tile t resident (this thread's groups)
        __syncthreads();         // everyone's loads visible

        uint32_t stg = sb + s * STAGE_FLOATS * 4;
        LOAD_FRAGS(0, stg, 0);   // prime ks=0
        LOAD_FRAGS(1, stg, 1);   // ks=1 in flight behind ks=0's MMAs
        MMA_BLOCK(0);
        LOAD_FRAGS(0, stg, 2);
        MMA_BLOCK(1);
        LOAD_FRAGS(1, stg, 3);
        MMA_BLOCK(0);
        MMA_BLOCK(1);

        __syncthreads();         // stage s reads done -> reusable as write target
        s = (s == 2) ? 0 : s + 1;
        sw = (sw == 2) ? 0 : sw + 1;
    }

    // epilogue: c0/c1 at (row g, cols 2t4..+1), c2/c3 at row g+8
#pragma unroll
    for (int mt = 0; mt < 4; mt++) {
        int mrow = m0 + wm * 64 + mt * 16 + g;
#pragma unroll
        for (int nt = 0; nt < 8; nt++) {
            int nc = n0 + wn * 64 + nt * 8 + 2 * t4;
            float bx = __ldg(b2 + nc), by = __ldg(b2 + nc + 1);
            float2 v0 = make_float2(acc[mt][nt][0] + bx, acc[mt][nt][1] + by);
            float2 v1 = make_float2(acc[mt][nt][2] + bx, acc[mt][nt][3] + by);
            *(float2*)(out + (size_t)mrow * CDIM + nc) = v0;
            *(float2*)(out + (size_t)(mrow + 8) * CDIM + nc) = v1;
        }
    }
}

// ==================== launch ====================
extern "C" void kernel_launch(void* const* d_in, const int* in_sizes, int n_in,
                              void* d_out, int out_size) {
    const float* x  = (const float*)d_in[0];
    // d_in[1] = circuit_params: provably cancels out of the measured expectations
    const float* w1 = (const float*)d_in[2];
    const float* b1 = (const float*)d_in[3];
    const float* w2 = (const float*)d_in[4];
    const float* b2 = (const float*)d_in[5];
    float* out = (float*)d_out;

    q_kernel<<<MTOK / 256, 256>>>(x);
    round_w2_kernel<<<(CDIM * FDIM) / (256 * 4), 256>>>(w2);
    h_kernel<<<dim3(FDIM / 32, MTOK / 512), 256>>>(w1, b1);

    cudaFuncSetAttribute(gemm2_kernel, cudaFuncAttributeMaxDynamicSharedMemorySize, SMEM_TOTAL);
    gemm2_kernel<<<dim3(CDIM / BN, MTOK / BM), 128, SMEM_TOTAL>>>(b2, out);
}

// round 15
// speedup vs baseline: 2.3220x; 2.0964x over previous
#include <cuda_runtime.h>
#include <cuda_fp16.h>
#include <cstdint>

#define MTOK 16384
#define FDIM 4096
#define CDIM 1024
#define NQ 8

#define BM 128
#define BN 128
#define BK 64
#define STAGES 3
#define KTILES (FDIM / BK)               // 64
#define SROWH 72                         // halves per smem row (144B: conflict-free LDSM phases)
#define A_HALVES (BM * SROWH)            // 9216
#define STAGE_BYTES (2 * A_HALVES * 2)   // 36864 (A then B)
#define SMEM_TOTAL (STAGES * STAGE_BYTES)        // 110592 -> 2 CTAs/SM

// ---- scratch (device globals; allocation is forbidden) ----
__device__ __align__(128) float  g_q[MTOK * NQ];                  // 512 KB
__device__ __align__(128) __half g_h[(size_t)MTOK * FDIM];        // 128 MB
__device__ __align__(128) __half g_w2h[(size_t)CDIM * FDIM];      // 8 MB

__device__ __forceinline__ uint32_t smem_u32(const void* p) {
    uint32_t a;
    asm("{ .reg .u64 t; cvta.to.shared.u64 t, %1; cvt.u32.u64 %0, t; }" : "=r"(a) : "l"(p));
    return a;
}

__device__ __forceinline__ void cp_async16(uint32_t dst, const void* src) {
    asm volatile("cp.async.cg.shared.global [%0], [%1], 16;" :: "r"(dst), "l"(src));
}
#define CP_COMMIT() asm volatile("cp.async.commit_group;" ::: "memory")
#define CP_WAIT2()  asm volatile("cp.async.wait_group 2;" ::: "memory")

// fp16 MMA, fp32 accumulator: same 10-bit mantissa as tf32, 2x MAC/instr.
__device__ __forceinline__ void mma_f16(float* c, const uint32_t* a, uint32_t b0, uint32_t b1) {
    asm volatile(
        "mma.sync.aligned.m16n8k16.row.col.f32.f16.f16.f32 "
        "{%0,%1,%2,%3}, {%4,%5,%6,%7}, {%8,%9}, {%0,%1,%2,%3};"
        : "+f"(c[0]), "+f"(c[1]), "+f"(c[2]), "+f"(c[3])
        : "r"(a[0]), "r"(a[1]), "r"(a[2]), "r"(a[3]), "r"(b0), "r"(b1));
}

__device__ __forceinline__ void ldsm4(uint32_t* r, uint32_t addr) {
    asm volatile("ldmatrix.sync.aligned.m8n8.x4.shared.b16 {%0,%1,%2,%3}, [%4];"
                 : "=r"(r[0]), "=r"(r[1]), "=r"(r[2]), "=r"(r[3]) : "r"(addr));
}

// ==================== pass 0: q = cumprod(cos(x[:, :8])) ====================
__global__ void __launch_bounds__(256) q_kernel(const float* __restrict__ x) {
    int tok = blockIdx.x * 256 + threadIdx.x;
    const float4* xp = (const float4*)(x + (size_t)tok * CDIM);
    float4 a = xp[0], b = xp[1];
    float q0 = cosf(a.x);
    float q1 = q0 * cosf(a.y);
    float q2 = q1 * cosf(a.z);
    float q3 = q2 * cosf(a.w);
    float q4 = q3 * cosf(b.x);
    float q5 = q4 * cosf(b.y);
    float q6 = q5 * cosf(b.z);
    float q7 = q6 * cosf(b.w);
    float4* qp = (float4*)(g_q + (size_t)tok * NQ);
    qp[0] = make_float4(q0, q1, q2, q3);
    qp[1] = make_float4(q4, q5, q6, q7);
}

// ==================== pass 0b: w2 -> fp16 ====================
__global__ void __launch_bounds__(256) w2h_kernel(const float* __restrict__ w2) {
    size_t i = (size_t)(blockIdx.x * 256 + threadIdx.x) * 4;
    float4 v = *(const float4*)(w2 + i);
    __half2* dst = (__half2*)(g_w2h + i);
    dst[0] = __floats2half2_rn(v.x, v.y);
    dst[1] = __floats2half2_rn(v.z, v.w);
}

// ==================== pass 1: h = relu(q @ w1^T + b1) -> fp16 ====================
// Each thread owns TWO adjacent f columns so stores are __half2 (coalesced 128B/warp).
__global__ void __launch_bounds__(256) h_kernel(const float* __restrict__ w1,
                                                const float* __restrict__ b1) {
    __shared__ float qs[512 * NQ];  // 16 KB
    int t = threadIdx.x;
    const float4* qg = (const float4*)(g_q + (size_t)blockIdx.y * 512 * NQ);
    float4* qs4 = (float4*)qs;
#pragma unroll
    for (int i = 0; i < 4; i++) qs4[t + i * 256] = qg[t + i * 256];
    __syncthreads();

    int f0 = blockIdx.x * 64 + (t & 31) * 2;
    int tok0 = (t >> 5) * 64;
    float4 wa0 = __ldg((const float4*)(w1 + (size_t)f0 * NQ));
    float4 wb0 = __ldg((const float4*)(w1 + (size_t)f0 * NQ + 4));
    float4 wa1 = __ldg((const float4*)(w1 + (size_t)(f0 + 1) * NQ));
    float4 wb1 = __ldg((const float4*)(w1 + (size_t)(f0 + 1) * NQ + 4));
    float bi0 = __ldg(b1 + f0), bi1 = __ldg(b1 + f0 + 1);
    __half* hp = g_h + ((size_t)(blockIdx.y * 512 + tok0)) * FDIM + f0;

#pragma unroll 4
    for (int i = 0; i < 64; i++) {
        const float4* qr = (const float4*)(qs + (tok0 + i) * NQ);
        float4 qa = qr[0], qb = qr[1];
        float v0 = bi0, v1 = bi1;
        v0 = fmaf(qa.x, wa0.x, v0); v1 = fmaf(qa.x, wa1.x, v1);
        v0 = fmaf(qa.y, wa0.y, v0); v1 = fmaf(qa.y, wa1.y, v1);
        v0 = fmaf(qa.z, wa0.z, v0); v1 = fmaf(qa.z, wa1.z, v1);
        v0 = fmaf(qa.w, wa0.w, v0); v1 = fmaf(qa.w, wa1.w, v1);
        v0 = fmaf(qb.x, wb0.x, v0); v1 = fmaf(qb.x, wb1.x, v1);
        v0 = fmaf(qb.y, wb0.y, v0); v1 = fmaf(qb.y, wb1.y, v1);
        v0 = fmaf(qb.z, wb0.z, v0); v1 = fmaf(qb.z, wb1.z, v1);
        v0 = fmaf(qb.w, wb0.w, v0); v1 = fmaf(qb.w, wb1.w, v1);
        *(__half2*)(hp + (size_t)i * FDIM) = __floats2half2_rn(fmaxf(v0, 0.0f), fmaxf(v1, 0.0f));
    }
}

// ==================== pass 2: out = h @ w2^T + b2 (mma.sync fp16, fp32 acc) ====
// CTA 128x128x64(fp16), 4 warps (2x2), warp tile 64x64; 3 stages, 2 CTAs/SM.
__device__ __forceinline__ void load_tile(uint32_t stage_b, int m0, int n0, int k0, int tid) {
    // A: 128 rows x 64 halves = 128B/row = 8 x 16B chunks
#pragma unroll
    for (int i = 0; i < 8; i++) {
        int idx = tid + i * 128;
        int row = idx >> 3, c16 = idx & 7;
        cp_async16(stage_b + row * (SROWH * 2) + c16 * 16,
                   (const char*)(g_h + (size_t)(m0 + row) * FDIM + k0) + c16 * 16);
    }
#pragma unroll
    for (int i = 0; i < 8; i++) {
        int idx = tid + i * 128;
        int row = idx >> 3, c16 = idx & 7;
        cp_async16(stage_b + A_HALVES * 2 + row * (SROWH * 2) + c16 * 16,
                   (const char*)(g_w2h + (size_t)(n0 + row) * FDIM + k0) + c16 * 16);
    }
}

__global__ void __launch_bounds__(128, 2) gemm2_kernel(const float* __restrict__ b2,
                                                       float* __restrict__ out) {
    extern __shared__ __align__(16) uint32_t sm[];
    uint32_t sb = smem_u32(sm);
    int tid = threadIdx.x, wid = tid >> 5, lane = tid & 31;
    int wm = wid & 1, wn = wid >> 1;          // warp grid 2 x 2; warp tile 64 x 64
    int g = lane >> 2, t4 = lane & 3;
    int m0 = blockIdx.y * BM, n0 = blockIdx.x * BN;

    float acc[4][8][4];
#pragma unroll
    for (int mt = 0; mt < 4; mt++)
#pragma unroll
        for (int nt = 0; nt < 8; nt++)
#pragma unroll
            for (int r = 0; r < 4; r++) acc[mt][nt][r] = 0.0f;

    // prologue: tiles 0,1 into stages 0,1
    load_tile(sb, m0, n0, 0, tid);                   CP_COMMIT();
    load_tile(sb + STAGE_BYTES, m0, n0, BK, tid);    CP_COMMIT();

    // A ldmatrix.x4: tiles (m0-7,k0) (m8-15,k0) (m0-7,k8) (m8-15,k8)
    //   -> regs match mma A frag a0..a3 exactly.
    const uint32_t aOff =
        ((uint32_t)(wm * 64 + (lane & 15)) * SROWH + ((lane >> 4) * 8)) * 2;
    // B ldmatrix.x4: tiles (n0-7,k0) (n0-7,k8) (n8-15,k0) (n8-15,k8)
    //   -> r0,r1 = b0,b1 of n-tile 2p; r2,r3 = b0,b1 of n-tile 2p+1.
    const uint32_t bOff = (uint32_t)(A_HALVES +
        ((wn * 64 + (lane & 7) + ((lane >> 4) << 3)) * SROWH + (((lane >> 3) & 1) * 8))) * 2;

    int s = 0, sw = 2;   // read stage, write stage (incremental mod-3)
    for (int t = 0; t < KTILES; t++) {
        if (t + 2 < KTILES)
            load_tile(sb + sw * STAGE_BYTES, m0, n0, (t + 2) * BK, tid);
        CP_COMMIT();             // uniform group accounting (empty at tail)
        CP_WAIT2();              // tile t resident (this thread's groups)
        __syncthreads();         // everyone's loads visible

        uint32_t stg = sb + s * STAGE_BYTES;
#pragma unroll
        for (int ks = 0; ks < 4; ks++) {       // 4 x k16
            uint32_t a[4][4], b[4][4];
#pragma unroll
            for (int mt = 0; mt < 4; mt++)
                ldsm4(a[mt], stg + aOff + (uint32_t)(mt * 16 * SROWH + ks * 16) * 2);
#pragma unroll
            for (int p = 0; p < 4; p++)
                ldsm4(b[p], stg + bOff + (uint32_t)(p * 16 * SROWH + ks * 16) * 2);
#pragma unroll
            for (int mt = 0; mt < 4; mt++)
#pragma unroll
                for (int p = 0; p < 4; p++) {
                    mma_f16(acc[mt][2 * p],     a[mt], b[p][0], b[p][1]);
                    mma_f16(acc[mt][2 * p + 1], a[mt], b[p][2], b[p][3]);
                }
        }
        __syncthreads();         // stage s reads done -> reusable as write target
        s = (s == 2) ? 0 : s + 1;
        sw = (sw == 2) ? 0 : sw + 1;
    }

    // epilogue: c0/c1 at (row g, cols 2t4..+1), c2/c3 at row g+8
#pragma unroll
    for (int mt = 0; mt < 4; mt++) {
        int mrow = m0 + wm * 64 + mt * 16 + g;
#pragma unroll
        for (int nt = 0; nt < 8; nt++) {
            int nc = n0 + wn * 64 + nt * 8 + 2 * t4;
            float bx = __ldg(b2 + nc), by = __ldg(b2 + nc + 1);
            float2 v0 = make_float2(acc[mt][nt][0] + bx, acc[mt][nt][1] + by);
            float2 v1 = make_float2(acc[mt][nt][2] + bx, acc[mt][nt][3] + by);
            *(float2*)(out + (size_t)mrow * CDIM + nc) = v0;
            *(float2*)(out + (size_t)(mrow + 8) * CDIM + nc) = v1;
        }
    }
}

// ==================== launch ====================
extern "C" void kernel_launch(void* const* d_in, const int* in_sizes, int n_in,
                              void* d_out, int out_size) {
    const float* x  = (const float*)d_in[0];
    // d_in[1] = circuit_params: provably cancels out of the measured expectations
    const float* w1 = (const float*)d_in[2];
    const float* b1 = (const float*)d_in[3];
    const float* w2 = (const float*)d_in[4];
    const float* b2 = (const float*)d_in[5];
    float* out = (float*)d_out;

    q_kernel<<<MTOK / 256, 256>>>(x);
    w2h_kernel<<<(CDIM * FDIM) / (256 * 4), 256>>>(w2);
    h_kernel<<<dim3(FDIM / 64, MTOK / 512), 256>>>(w1, b1);

    cudaFuncSetAttribute(gemm2_kernel, cudaFuncAttributeMaxDynamicSharedMemorySize, SMEM_TOTAL);
    gemm2_kernel<<<dim3(CDIM / BN, MTOK / BM), 128, SMEM_TOTAL>>>(b2, out);
}